// round 8
// baseline (speedup 1.0000x reference)
#include <cuda_runtime.h>
#include <math.h>
#include <stdint.h>

#define NN    5000
#define EE    50000
#define LL    9
#define CC    128
#define NHEAD 8
#define NLROWS (NN*LL)   // 45000

// ------------------------- device scratch (static, no allocs) -------------------------
__device__ float g_Y[NLROWS*256];
__device__ float g_WmsgC[128*256];
__device__ float g_bz[100*128];
__device__ float g_cz[100*128];
__device__ float g_u[8*128];
__device__ float g_hidden[EE*128];
__device__ float g_rad[EE*128];
__device__ float g_msg0[(size_t)EE*128];
__device__ float g_S[(size_t)EE*72];
__device__ float g_abuf[(size_t)EE*256];
__device__ float g_logits[EE*8];
__device__ float g_ex[EE*8];
__device__ float g_m[NN*8];
__device__ float g_den[NN*8];
__device__ float g_outv[NN*3];
__device__ float g_outd[NN*3];
__device__ unsigned int g_maskinfo[1];

// ------------------------- helpers -------------------------
__device__ __forceinline__ float siluf(float x) { return x / (1.f + __expf(-x)); }
__device__ __forceinline__ float sigmf(float x) { return 1.f / (1.f + __expf(-x)); }

__device__ __forceinline__ void atomicMaxFloat(float* addr, float val) {
    if (val >= 0.f) atomicMax((int*)addr, __float_as_int(val));
    else            atomicMin((unsigned int*)addr, __float_as_uint(val));
}

__device__ __forceinline__ uint32_t tf32r(float x) {
    uint32_t r;
    asm("cvt.rna.tf32.f32 %0, %1;" : "=r"(r) : "f"(x));
    return r;
}

__device__ __forceinline__ void mma_tf32(float c[4], uint32_t a0, uint32_t a1, uint32_t a2, uint32_t a3,
                                         uint32_t b0, uint32_t b1) {
    asm volatile("mma.sync.aligned.m16n8k8.row.col.f32.tf32.tf32.f32 "
                 "{%0,%1,%2,%3}, {%4,%5,%6,%7}, {%8,%9}, {%0,%1,%2,%3};"
                 : "+f"(c[0]), "+f"(c[1]), "+f"(c[2]), "+f"(c[3])
                 : "r"(a0), "r"(a1), "r"(a2), "r"(a3), "r"(b0), "r"(b1));
}

// ------------------------- init / mask detect -------------------------
__global__ void k_init0() {
    int tid = blockIdx.x * blockDim.x + threadIdx.x;
    if (tid < NN*3) { g_outv[tid] = 0.f; g_outd[tid] = 0.f; }
    if (tid == 0) g_maskinfo[0] = 0u;
}

__global__ void k_detect_mask(const unsigned int* __restrict__ mask) {
    int tid = blockIdx.x * blockDim.x + threadIdx.x;
    if (tid >= NN/4) return;
    unsigned int w = mask[tid];
    if (w == 0x3F800000u)      atomicOr(g_maskinfo, 2u);
    else if (w > 1u)           atomicOr(g_maskinfo, 1u);
}

__global__ void k_init_mden() {
    int tid = blockIdx.x * blockDim.x + threadIdx.x;
    if (tid < NN*8) { g_m[tid] = __int_as_float(0xFF800000); g_den[tid] = 0.f; }
}

// ------------------------- tiny precompute kernels -------------------------
__global__ void k_pack_wmsg(const float* __restrict__ Wmsg) {
    int idx = blockIdx.x * blockDim.x + threadIdx.x;
    if (idx >= 128*256) return;
    int k = idx >> 8, c = idx & 255;
    g_WmsgC[idx] = (c < 128) ? Wmsg[k*128 + c] : Wmsg[(128 + k)*128 + (c - 128)];
}

__global__ void k_zemb(const float* __restrict__ ae, const float* __restrict__ Wrad1) {
    int z = blockIdx.x, c = threadIdx.x;
    __shared__ float aes[64];
    if (c < 64) aes[c] = ae[z*64 + c];
    __syncthreads();
    float sb = 0.f, sc = 0.f;
    #pragma unroll 8
    for (int k = 0; k < 64; k++) {
        float a = aes[k];
        sb += a * Wrad1[(128 + k)*128 + c];
        sc += a * Wrad1[(192 + k)*128 + c];
    }
    g_bz[z*128 + c] = sb;
    g_cz[z*128 + c] = sc;
}

__global__ void k_uvec(const float* __restrict__ Wval, const float* __restrict__ Wproj) {
    int h = blockIdx.x, c = threadIdx.x;
    float s = 0.f;
    #pragma unroll
    for (int vc = 0; vc < 16; vc++)
        s += Wval[c*128 + h*16 + vc] * Wproj[h*16 + vc];
    g_u[h*128 + c] = s;
}

// ------------------------- tf32 tensor-core GEMM -------------------------
#define PAD 4
template<int EPI>
__global__ __launch_bounds__(256)
void k_gemm_tc(const float* __restrict__ A, int lda,
               const float* __restrict__ W, int ldw,
               float* __restrict__ Cout, int ldc, int M,
               const int* __restrict__ srcA, const int* __restrict__ dstA,
               const int* __restrict__ zA)
{
    __shared__ float As[16][128 + PAD];
    __shared__ float Ws[16][128 + PAD];

    const int tid  = threadIdx.x;
    const int lane = tid & 31;
    const int warp = tid >> 5;
    const int wm   = warp & 3;
    const int wn   = warp >> 2;
    const int m0   = blockIdx.x * 128;
    const int n0   = blockIdx.y * 128;

    const int g    = lane >> 2;
    const int tg   = lane & 3;

    const int arow = tid >> 1;
    const int akq  = (tid & 1) * 8;
    const int wrow = tid >> 4;
    const int wcol = (tid & 15) * 8;

    float acc[2][8][4];
    #pragma unroll
    for (int mi = 0; mi < 2; mi++)
        #pragma unroll
        for (int ni = 0; ni < 8; ni++)
            #pragma unroll
            for (int r = 0; r < 4; r++) acc[mi][ni][r] = 0.f;

    for (int k0 = 0; k0 < 128; k0 += 16) {
        {
            int row = m0 + arow;
            float4 v0 = make_float4(0.f,0.f,0.f,0.f), v1 = v0;
            if (row < M) {
                const float* ap = A + (size_t)row*lda + k0 + akq;
                v0 = *(const float4*)ap;
                v1 = *(const float4*)(ap + 4);
            }
            As[akq + 0][arow] = __uint_as_float(tf32r(v0.x));
            As[akq + 1][arow] = __uint_as_float(tf32r(v0.y));
            As[akq + 2][arow] = __uint_as_float(tf32r(v0.z));
            As[akq + 3][arow] = __uint_as_float(tf32r(v0.w));
            As[akq + 4][arow] = __uint_as_float(tf32r(v1.x));
            As[akq + 5][arow] = __uint_as_float(tf32r(v1.y));
            As[akq + 6][arow] = __uint_as_float(tf32r(v1.z));
            As[akq + 7][arow] = __uint_as_float(tf32r(v1.w));
        }
        {
            const float* wp = W + (size_t)(k0 + wrow)*ldw + n0 + wcol;
            float4 v0 = *(const float4*)wp;
            float4 v1 = *(const float4*)(wp + 4);
            Ws[wrow][wcol + 0] = __uint_as_float(tf32r(v0.x));
            Ws[wrow][wcol + 1] = __uint_as_float(tf32r(v0.y));
            Ws[wrow][wcol + 2] = __uint_as_float(tf32r(v0.z));
            Ws[wrow][wcol + 3] = __uint_as_float(tf32r(v0.w));
            Ws[wrow][wcol + 4] = __uint_as_float(tf32r(v1.x));
            Ws[wrow][wcol + 5] = __uint_as_float(tf32r(v1.y));
            Ws[wrow][wcol + 6] = __uint_as_float(tf32r(v1.z));
            Ws[wrow][wcol + 7] = __uint_as_float(tf32r(v1.w));
        }
        __syncthreads();

        #pragma unroll
        for (int ki = 0; ki < 16; ki += 8) {
            uint32_t afrag[2][4];
            #pragma unroll
            for (int mi = 0; mi < 2; mi++) {
                int m = wm*32 + mi*16 + g;
                afrag[mi][0] = __float_as_uint(As[ki + tg    ][m    ]);
                afrag[mi][1] = __float_as_uint(As[ki + tg    ][m + 8]);
                afrag[mi][2] = __float_as_uint(As[ki + tg + 4][m    ]);
                afrag[mi][3] = __float_as_uint(As[ki + tg + 4][m + 8]);
            }
            #pragma unroll
            for (int ni = 0; ni < 8; ni++) {
                int n = wn*64 + ni*8 + g;
                uint32_t b0 = __float_as_uint(Ws[ki + tg    ][n]);
                uint32_t b1 = __float_as_uint(Ws[ki + tg + 4][n]);
                mma_tf32(acc[0][ni], afrag[0][0], afrag[0][1], afrag[0][2], afrag[0][3], b0, b1);
                mma_tf32(acc[1][ni], afrag[1][0], afrag[1][1], afrag[1][2], afrag[1][3], b0, b1);
            }
        }
        __syncthreads();
    }

    #pragma unroll
    for (int mi = 0; mi < 2; mi++) {
        #pragma unroll
        for (int r = 0; r < 2; r++) {
            int row = m0 + wm*32 + mi*16 + g + r*8;
            if (row >= M) continue;
            int colbase = n0 + wn*64 + 2*tg;
            if (EPI == 1) {
                int zs = zA[srcA[row]], zd = zA[dstA[row]];
                #pragma unroll
                for (int ni = 0; ni < 8; ni++) {
                    int col = colbase + ni*8;
                    float c0 = acc[mi][ni][r*2 + 0];
                    float c1 = acc[mi][ni][r*2 + 1];
                    c0 = siluf(c0 + g_bz[zs*128 + col]     + g_cz[zd*128 + col]);
                    c1 = siluf(c1 + g_bz[zs*128 + col + 1] + g_cz[zd*128 + col + 1]);
                    *(float2*)(Cout + (size_t)row*ldc + col) = make_float2(c0, c1);
                }
            } else {
                #pragma unroll
                for (int ni = 0; ni < 8; ni++) {
                    int col = colbase + ni*8;
                    *(float2*)(Cout + (size_t)row*ldc + col) =
                        make_float2(acc[mi][ni][r*2 + 0], acc[mi][ni][r*2 + 1]);
                }
            }
        }
    }
}

// ------------------------- pass 1: msg0 + S[e,j,h], no msg materialization -------------------------
__global__ __launch_bounds__(256)
void k_fuse1(const float* __restrict__ wigner,
             const int* __restrict__ src, const int* __restrict__ dst)
{
    const int warp = threadIdx.x >> 5, lane = threadIdx.x & 31;
    const int e = blockIdx.x * 8 + warp;
    if (e >= EE) return;

    float4 uh[8];
    #pragma unroll
    for (int h = 0; h < 8; h++) uh[h] = ((const float4*)g_u)[h*32 + lane];

    float w0 = (lane < 9) ? wigner[(size_t)e*81 + lane] : 0.f;
    const int s = src[e], d = dst[e];
    const float4* Ys = (const float4*)g_Y + (size_t)s*9*64 + lane;
    const float4* Yd = (const float4*)g_Y + (size_t)d*9*64 + 32 + lane;

    float4 t[9];
    #pragma unroll
    for (int j = 0; j < 9; j++) {
        float4 a = Ys[j*64], b = Yd[j*64];
        t[j] = make_float4(a.x + b.x, a.y + b.y, a.z + b.z, a.w + b.w);
    }

    float4 r4 = ((const float4*)g_rad)[(size_t)e*32 + lane];

    float4 m0 = make_float4(0.f, 0.f, 0.f, 0.f);
    #pragma unroll
    for (int j = 0; j < 9; j++) {
        float w = __shfl_sync(0xffffffffu, w0, j);
        m0.x += w*t[j].x; m0.y += w*t[j].y; m0.z += w*t[j].z; m0.w += w*t[j].w;
    }
    m0.x *= r4.x; m0.y *= r4.y; m0.z *= r4.z; m0.w *= r4.w;
    ((float4*)g_msg0)[(size_t)e*32 + lane] = m0;

    float4 z = make_float4(sigmf(m0.x)*r4.x, sigmf(m0.y)*r4.y, sigmf(m0.z)*r4.z, sigmf(m0.w)*r4.w);

    const int myh = (lane >> 2) & 7;
    #pragma unroll
    for (int j = 0; j < 9; j++) {
        float4 tz = make_float4(t[j].x*z.x, t[j].y*z.y, t[j].z*z.z, t[j].w*z.w);
        float p[8];
        #pragma unroll
        for (int h = 0; h < 8; h++)
            p[h] = tz.x*uh[h].x + tz.y*uh[h].y + tz.z*uh[h].z + tz.w*uh[h].w;
        // value-splitting butterfly: 8 items -> 1 per lane quad (all shfls lane-uniform)
        {
            bool up = (lane & 16);
            float q[4];
            #pragma unroll
            for (int i = 0; i < 4; i++) {
                float got = __shfl_xor_sync(0xffffffffu, p[(up ? 0 : 4) + i], 16);
                q[i] = p[(up ? 4 : 0) + i] + got;
            }
            bool up8 = (lane & 8);
            float q2[2];
            #pragma unroll
            for (int i = 0; i < 2; i++) {
                float got = __shfl_xor_sync(0xffffffffu, q[(up8 ? 0 : 2) + i], 8);
                q2[i] = q[(up8 ? 2 : 0) + i] + got;
            }
            bool up4 = (lane & 4);
            float got = __shfl_xor_sync(0xffffffffu, q2[up4 ? 0 : 1], 4);
            float v = q2[up4 ? 1 : 0] + got;
            v += __shfl_xor_sync(0xffffffffu, v, 1);
            v += __shfl_xor_sync(0xffffffffu, v, 2);
            if ((lane & 3) == 0)
                g_S[(size_t)e*72 + j*8 + myh] = v;
        }
    }
}

// ------------------------- logits + segment max -------------------------
__global__ void k_logits(const float* __restrict__ avec, const int* __restrict__ dst)
{
    const int warp = threadIdx.x >> 5, lane = threadIdx.x & 31;
    const int e = blockIdx.x * 8 + warp;
    if (e >= EE) return;
    const float4* ap = (const float4*)(g_abuf + (size_t)e*256) + lane*2;
    const float4* vp = (const float4*)avec + lane*2;
    float4 a0 = ap[0], a1 = ap[1];
    float4 v0 = vp[0], v1 = vp[1];
    #define LR(x) ((x) > 0.f ? (x) : 0.2f*(x))
    float p = LR(a0.x)*v0.x + LR(a0.y)*v0.y + LR(a0.z)*v0.z + LR(a0.w)*v0.w
            + LR(a1.x)*v1.x + LR(a1.y)*v1.y + LR(a1.z)*v1.z + LR(a1.w)*v1.w;
    #undef LR
    p += __shfl_xor_sync(0xffffffffu, p, 1);
    p += __shfl_xor_sync(0xffffffffu, p, 2);
    if ((lane & 3) == 0) {
        int h = lane >> 2;
        g_logits[(size_t)e*8 + h] = p;
        atomicMaxFloat(&g_m[dst[e]*8 + h], p);
    }
}

__global__ void k_expsum(const int* __restrict__ dst)
{
    int tid = blockIdx.x * blockDim.x + threadIdx.x;
    if (tid >= EE*8) return;
    int e = tid >> 3, h = tid & 7;
    int d = dst[e];
    float ex = __expf(g_logits[tid] - g_m[d*8 + h]);
    g_ex[tid] = ex;
    atomicAdd(&g_den[d*8 + h], ex);
}

// ------------------------- pass 2: attn -> R_j -> wigner gram -> scatter -------------------------
__global__ __launch_bounds__(256)
void k_edge_out2(const float* __restrict__ wigner,
                 const int* __restrict__ dst, float* __restrict__ outp)
{
    const int warp = threadIdx.x >> 5, lane = threadIdx.x & 31;
    const int e = blockIdx.x * 8 + warp;
    if (e >= EE) return;
    const int d = dst[e];

    float attn = 0.f;
    if (lane < 8) attn = g_ex[(size_t)e*8 + lane] / (g_den[d*8 + lane] + 1e-9f);

    // R_j = sum_h attn_h * S[e][j*8+h]  — shfl kept lane-uniform; loads predicated
    float R = 0.f;
    {
        const float* Sp = g_S + (size_t)e*72 + lane*8;   // only dereferenced when lane<9
        #pragma unroll
        for (int h = 0; h < 8; h++) {
            float ah = __shfl_sync(0xffffffffu, attn, h);
            float sv = 0.f;
            if (lane < 9) sv = Sp[h];
            R += ah * sv;
        }
    }

    // c_l = sum_j wig[l][j] * R_j
    float c = 0.f;
    {
        const float* wl = wigner + (size_t)e*81 + lane*9;
        #pragma unroll
        for (int j = 0; j < 9; j++) {
            float Rj = __shfl_sync(0xffffffffu, R, j);
            if (lane < 9) c += wl[j] * Rj;
        }
    }

    // out_i = sum_l wig[l][i+1] * c_l
    float o = 0.f;
    {
        #pragma unroll
        for (int l = 0; l < 9; l++) {
            float cl = __shfl_sync(0xffffffffu, c, l);
            if (lane < 3) o += wigner[(size_t)e*81 + l*9 + (lane + 1)] * cl;
        }
    }
    if (lane < 3) atomicAdd(&outp[d*3 + lane], o);
}

// ------------------------- final select -------------------------
__global__ void k_final(const unsigned char* __restrict__ mask, float* __restrict__ out)
{
    int tid = blockIdx.x * blockDim.x + threadIdx.x;
    if (tid >= NN*3) return;
    int n = tid / 3;
    unsigned int info = g_maskinfo[0];
    bool mk;
    if (info & 2u)      mk = (((const float*)mask)[n] != 0.f);
    else if (info & 1u) mk = (mask[n] != 0);
    else                mk = (((const int*)mask)[n] != 0);
    out[tid] = mk ? g_outd[tid] : g_outv[tid];
}

// ------------------------- host launch -------------------------
extern "C" void kernel_launch(void* const* d_in, const int* in_sizes, int n_in,
                              void* d_out, int out_size)
{
    float *pY, *pWmsgC, *pHidden, *pRad, *pMsg0, *pA, *pOutv, *pOutd;
    cudaGetSymbolAddress((void**)&pY, g_Y);
    cudaGetSymbolAddress((void**)&pWmsgC, g_WmsgC);
    cudaGetSymbolAddress((void**)&pHidden, g_hidden);
    cudaGetSymbolAddress((void**)&pRad, g_rad);
    cudaGetSymbolAddress((void**)&pMsg0, g_msg0);
    cudaGetSymbolAddress((void**)&pA, g_abuf);
    cudaGetSymbolAddress((void**)&pOutv, g_outv);
    cudaGetSymbolAddress((void**)&pOutd, g_outd);

    const float* node_emb  = (const float*)d_in[0];
    const float* edge_dist = (const float*)d_in[1];
    const float* wigner    = (const float*)d_in[2];
    const int *atomic_numbers, *edge_index;
    const void* mask;
    int pbase[2];
    bool dictOrder = (in_sizes[3] == NN);
    if (dictOrder) {
        atomic_numbers = (const int*)d_in[3];
        edge_index     = (const int*)d_in[4];
        mask           = d_in[5];
        pbase[0] = 6; pbase[1] = 14;
    } else {
        pbase[0] = 3; pbase[1] = 11;
        atomic_numbers = (const int*)d_in[19];
        edge_index     = (const int*)d_in[20];
        mask           = d_in[21];
    }
    const int* src = edge_index;
    const int* dst = edge_index + EE;

    k_init0<<<(NN*3 + 255)/256, 256>>>();
    k_detect_mask<<<(NN/4 + 255)/256, 256>>>((const unsigned int*)mask);

    for (int t = 0; t < 2; t++) {
        int b = pbase[t];
        const float* ae     = (const float*)d_in[b + 0];
        const float* Wrad1  = (const float*)d_in[b + 1];
        const float* Wrad2  = (const float*)d_in[b + 2];
        const float* Wmsg   = (const float*)d_in[b + 3];
        const float* Walpha = (const float*)d_in[b + 4];
        const float* avec   = (const float*)d_in[b + 5];
        const float* Wval   = (const float*)d_in[b + 6];
        const float* Wproj  = (const float*)d_in[b + 7];

        k_pack_wmsg<<<128, 256>>>(Wmsg);
        // Y GEMM placed as global launch #4 so the ncu -s5-c1 window captures it
        k_gemm_tc<0><<<dim3((NLROWS + 127)/128, 2), 256>>>(node_emb, 128, pWmsgC, 256, pY, 256, NLROWS,
                                                           nullptr, nullptr, nullptr);
        k_zemb<<<100, 128>>>(ae, Wrad1);
        k_uvec<<<8, 128>>>(Wval, Wproj);

        // hidden = silu(dist @ W1a + bz[z_src] + cz[z_dst])
        k_gemm_tc<1><<<dim3((EE + 127)/128, 1), 256>>>(edge_dist, 128, Wrad1, 128, pHidden, 128, EE,
                                                       src, dst, atomic_numbers);
        // rad = hidden @ W_rad2
        k_gemm_tc<0><<<dim3((EE + 127)/128, 1), 256>>>(pHidden, 128, Wrad2, 128, pRad, 128, EE,
                                                       nullptr, nullptr, nullptr);
        // fused: msg0 + S (replaces full msg materialization)
        k_fuse1<<<(EE + 7)/8, 256>>>(wigner, src, dst);
        // a = msg0 @ W_alpha
        k_gemm_tc<0><<<dim3((EE + 127)/128, 2), 256>>>(pMsg0, 128, Walpha, 256, pA, 256, EE,
                                                       nullptr, nullptr, nullptr);
        // segment softmax
        k_init_mden<<<(NN*8 + 255)/256, 256>>>();
        k_logits<<<(EE + 7)/8, 256>>>(avec, dst);
        k_expsum<<<(EE*8 + 255)/256, 256>>>(dst);
        // pass 2
        k_edge_out2<<<(EE + 7)/8, 256>>>(wigner, dst, (t == 0) ? pOutv : pOutd);
    }

    k_final<<<(NN*3 + 255)/256, 256>>>((const unsigned char*)mask, (float*)d_out);
}

// round 9
// speedup vs baseline: 1.0277x; 1.0277x over previous
#include <cuda_runtime.h>
#include <math.h>
#include <stdint.h>

#define NN    5000
#define EE    50000
#define LL    9
#define CC    128
#define NHEAD 8
#define NLROWS (NN*LL)   // 45000

// ------------------------- device scratch (static, no allocs) -------------------------
__device__ float g_Y[NLROWS*256];
__device__ float g_WmsgC[128*256];
__device__ float g_bz[100*128];
__device__ float g_cz[100*128];
__device__ float g_u[8*128];
__device__ float g_hidden[EE*128];
__device__ float g_rad[EE*128];
__device__ float g_msg0[(size_t)EE*128];
__device__ float g_S[(size_t)EE*72];
__device__ float g_abuf[(size_t)EE*256];
__device__ float g_logits[EE*8];
__device__ float g_ex[EE*8];
__device__ float g_m[NN*8];
__device__ float g_den[NN*8];
__device__ float g_outv[NN*3];
__device__ float g_outd[NN*3];
__device__ unsigned int g_maskinfo[1];

// ------------------------- helpers -------------------------
__device__ __forceinline__ float siluf(float x) { return x / (1.f + __expf(-x)); }
__device__ __forceinline__ float sigmf(float x) { return 1.f / (1.f + __expf(-x)); }

__device__ __forceinline__ void atomicMaxFloat(float* addr, float val) {
    if (val >= 0.f) atomicMax((int*)addr, __float_as_int(val));
    else            atomicMin((unsigned int*)addr, __float_as_uint(val));
}

__device__ __forceinline__ uint32_t tf32r(float x) {
    uint32_t r;
    asm("cvt.rna.tf32.f32 %0, %1;" : "=r"(r) : "f"(x));
    return r;
}

__device__ __forceinline__ void mma_tf32(float c[4], uint32_t a0, uint32_t a1, uint32_t a2, uint32_t a3,
                                         uint32_t b0, uint32_t b1) {
    asm volatile("mma.sync.aligned.m16n8k8.row.col.f32.tf32.tf32.f32 "
                 "{%0,%1,%2,%3}, {%4,%5,%6,%7}, {%8,%9}, {%0,%1,%2,%3};"
                 : "+f"(c[0]), "+f"(c[1]), "+f"(c[2]), "+f"(c[3])
                 : "r"(a0), "r"(a1), "r"(a2), "r"(a3), "r"(b0), "r"(b1));
}

// ------------------------- init / mask detect -------------------------
__global__ void k_init0() {
    int tid = blockIdx.x * blockDim.x + threadIdx.x;
    if (tid < NN*3) { g_outv[tid] = 0.f; g_outd[tid] = 0.f; }
    if (tid == 0) g_maskinfo[0] = 0u;
}

__global__ void k_detect_mask(const unsigned int* __restrict__ mask) {
    int tid = blockIdx.x * blockDim.x + threadIdx.x;
    if (tid >= NN/4) return;
    unsigned int w = mask[tid];
    if (w == 0x3F800000u)      atomicOr(g_maskinfo, 2u);
    else if (w > 1u)           atomicOr(g_maskinfo, 1u);
}

__global__ void k_init_mden() {
    int tid = blockIdx.x * blockDim.x + threadIdx.x;
    if (tid < NN*8) { g_m[tid] = __int_as_float(0xFF800000); g_den[tid] = 0.f; }
}

// ------------------------- tiny precompute kernels -------------------------
__global__ void k_pack_wmsg(const float* __restrict__ Wmsg) {
    int idx = blockIdx.x * blockDim.x + threadIdx.x;
    if (idx >= 128*256) return;
    int k = idx >> 8, c = idx & 255;
    g_WmsgC[idx] = (c < 128) ? Wmsg[k*128 + c] : Wmsg[(128 + k)*128 + (c - 128)];
}

__global__ void k_zemb(const float* __restrict__ ae, const float* __restrict__ Wrad1) {
    int z = blockIdx.x, c = threadIdx.x;
    __shared__ float aes[64];
    if (c < 64) aes[c] = ae[z*64 + c];
    __syncthreads();
    float sb = 0.f, sc = 0.f;
    #pragma unroll 8
    for (int k = 0; k < 64; k++) {
        float a = aes[k];
        sb += a * Wrad1[(128 + k)*128 + c];
        sc += a * Wrad1[(192 + k)*128 + c];
    }
    g_bz[z*128 + c] = sb;
    g_cz[z*128 + c] = sc;
}

__global__ void k_uvec(const float* __restrict__ Wval, const float* __restrict__ Wproj) {
    int h = blockIdx.x, c = threadIdx.x;
    float s = 0.f;
    #pragma unroll
    for (int vc = 0; vc < 16; vc++)
        s += Wval[c*128 + h*16 + vc] * Wproj[h*16 + vc];
    g_u[h*128 + c] = s;
}

// ------------------------- tf32 tensor-core GEMM, software-pipelined K loop -------------------------
#define PAD 4
template<int EPI>
__global__ __launch_bounds__(256, 2)
void k_gemm_tc(const float* __restrict__ A, int lda,
               const float* __restrict__ W, int ldw,
               float* __restrict__ Cout, int ldc, int M,
               const int* __restrict__ srcA, const int* __restrict__ dstA,
               const int* __restrict__ zA)
{
    __shared__ float As[16][128 + PAD];
    __shared__ float Ws[16][128 + PAD];

    const int tid  = threadIdx.x;
    const int lane = tid & 31;
    const int warp = tid >> 5;
    const int wm   = warp & 3;
    const int wn   = warp >> 2;
    const int m0   = blockIdx.x * 128;
    const int n0   = blockIdx.y * 128;

    const int g    = lane >> 2;
    const int tg   = lane & 3;

    const int arow = tid >> 1;
    const int akq  = (tid & 1) * 8;
    const int wrow = tid >> 4;
    const int wcol = (tid & 15) * 8;

    const int   rowA  = m0 + arow;
    const bool  rowOK = (rowA < M);
    const float* ap = A + (size_t)rowA*lda + akq;
    const float* wp = W + (size_t)wrow*ldw + n0 + wcol;

    float acc[2][8][4];
    #pragma unroll
    for (int mi = 0; mi < 2; mi++)
        #pragma unroll
        for (int ni = 0; ni < 8; ni++)
            #pragma unroll
            for (int r = 0; r < 4; r++) acc[mi][ni][r] = 0.f;

    // prologue: stage tile k0=0 into registers
    float4 pa0 = make_float4(0.f,0.f,0.f,0.f), pa1 = pa0;
    if (rowOK) { pa0 = *(const float4*)ap; pa1 = *(const float4*)(ap + 4); }
    float4 pw0 = *(const float4*)wp;
    float4 pw1 = *(const float4*)(wp + 4);

    for (int k0 = 0; k0 < 128; k0 += 16) {
        // store staged tile to smem (tf32 rounding on store)
        As[akq + 0][arow] = __uint_as_float(tf32r(pa0.x));
        As[akq + 1][arow] = __uint_as_float(tf32r(pa0.y));
        As[akq + 2][arow] = __uint_as_float(tf32r(pa0.z));
        As[akq + 3][arow] = __uint_as_float(tf32r(pa0.w));
        As[akq + 4][arow] = __uint_as_float(tf32r(pa1.x));
        As[akq + 5][arow] = __uint_as_float(tf32r(pa1.y));
        As[akq + 6][arow] = __uint_as_float(tf32r(pa1.z));
        As[akq + 7][arow] = __uint_as_float(tf32r(pa1.w));
        Ws[wrow][wcol + 0] = __uint_as_float(tf32r(pw0.x));
        Ws[wrow][wcol + 1] = __uint_as_float(tf32r(pw0.y));
        Ws[wrow][wcol + 2] = __uint_as_float(tf32r(pw0.z));
        Ws[wrow][wcol + 3] = __uint_as_float(tf32r(pw0.w));
        Ws[wrow][wcol + 4] = __uint_as_float(tf32r(pw1.x));
        Ws[wrow][wcol + 5] = __uint_as_float(tf32r(pw1.y));
        Ws[wrow][wcol + 6] = __uint_as_float(tf32r(pw1.z));
        Ws[wrow][wcol + 7] = __uint_as_float(tf32r(pw1.w));
        __syncthreads();

        // prefetch next tile into registers (overlaps with MMA below)
        if (k0 + 16 < 128) {
            if (rowOK) {
                pa0 = *(const float4*)(ap + k0 + 16);
                pa1 = *(const float4*)(ap + k0 + 20);
            }
            pw0 = *(const float4*)(wp + (size_t)(k0 + 16)*ldw);
            pw1 = *(const float4*)(wp + (size_t)(k0 + 16)*ldw + 4);
        }

        #pragma unroll
        for (int ki = 0; ki < 16; ki += 8) {
            uint32_t afrag[2][4];
            #pragma unroll
            for (int mi = 0; mi < 2; mi++) {
                int m = wm*32 + mi*16 + g;
                afrag[mi][0] = __float_as_uint(As[ki + tg    ][m    ]);
                afrag[mi][1] = __float_as_uint(As[ki + tg    ][m + 8]);
                afrag[mi][2] = __float_as_uint(As[ki + tg + 4][m    ]);
                afrag[mi][3] = __float_as_uint(As[ki + tg + 4][m + 8]);
            }
            #pragma unroll
            for (int ni = 0; ni < 8; ni++) {
                int n = wn*64 + ni*8 + g;
                uint32_t b0 = __float_as_uint(Ws[ki + tg    ][n]);
                uint32_t b1 = __float_as_uint(Ws[ki + tg + 4][n]);
                mma_tf32(acc[0][ni], afrag[0][0], afrag[0][1], afrag[0][2], afrag[0][3], b0, b1);
                mma_tf32(acc[1][ni], afrag[1][0], afrag[1][1], afrag[1][2], afrag[1][3], b0, b1);
            }
        }
        __syncthreads();
    }

    #pragma unroll
    for (int mi = 0; mi < 2; mi++) {
        #pragma unroll
        for (int r = 0; r < 2; r++) {
            int row = m0 + wm*32 + mi*16 + g + r*8;
            if (row >= M) continue;
            int colbase = n0 + wn*64 + 2*tg;
            if (EPI == 1) {
                int zs = zA[srcA[row]], zd = zA[dstA[row]];
                #pragma unroll
                for (int ni = 0; ni < 8; ni++) {
                    int col = colbase + ni*8;
                    float c0 = acc[mi][ni][r*2 + 0];
                    float c1 = acc[mi][ni][r*2 + 1];
                    c0 = siluf(c0 + g_bz[zs*128 + col]     + g_cz[zd*128 + col]);
                    c1 = siluf(c1 + g_bz[zs*128 + col + 1] + g_cz[zd*128 + col + 1]);
                    *(float2*)(Cout + (size_t)row*ldc + col) = make_float2(c0, c1);
                }
            } else {
                #pragma unroll
                for (int ni = 0; ni < 8; ni++) {
                    int col = colbase + ni*8;
                    *(float2*)(Cout + (size_t)row*ldc + col) =
                        make_float2(acc[mi][ni][r*2 + 0], acc[mi][ni][r*2 + 1]);
                }
            }
        }
    }
}

// ------------------------- pass 1: msg0 + S[e,j,h]; u in shared to cut register pressure -------------------------
__global__ __launch_bounds__(256)
void k_fuse1(const float* __restrict__ wigner,
             const int* __restrict__ src, const int* __restrict__ dst)
{
    __shared__ float4 us[8][32];
    const int tid  = threadIdx.x;
    const int warp = tid >> 5, lane = tid & 31;

    us[tid >> 5][tid & 31] = ((const float4*)g_u)[tid];   // 256 threads = 256 float4s exactly
    __syncthreads();

    const int e = blockIdx.x * 8 + warp;                   // EE = 6250*8 exactly, no stragglers
    if (e >= EE) return;

    float w0 = (lane < 9) ? wigner[(size_t)e*81 + lane] : 0.f;
    const int s = src[e], d = dst[e];
    const float4* Ys = (const float4*)g_Y + (size_t)s*9*64 + lane;
    const float4* Yd = (const float4*)g_Y + (size_t)d*9*64 + 32 + lane;

    float4 t[9];
    #pragma unroll
    for (int j = 0; j < 9; j++) {
        float4 a = Ys[j*64], b = Yd[j*64];
        t[j] = make_float4(a.x + b.x, a.y + b.y, a.z + b.z, a.w + b.w);
    }

    float4 r4 = ((const float4*)g_rad)[(size_t)e*32 + lane];

    float4 m0 = make_float4(0.f, 0.f, 0.f, 0.f);
    #pragma unroll
    for (int j = 0; j < 9; j++) {
        float w = __shfl_sync(0xffffffffu, w0, j);
        m0.x += w*t[j].x; m0.y += w*t[j].y; m0.z += w*t[j].z; m0.w += w*t[j].w;
    }
    m0.x *= r4.x; m0.y *= r4.y; m0.z *= r4.z; m0.w *= r4.w;
    ((float4*)g_msg0)[(size_t)e*32 + lane] = m0;

    float4 z = make_float4(sigmf(m0.x)*r4.x, sigmf(m0.y)*r4.y, sigmf(m0.z)*r4.z, sigmf(m0.w)*r4.w);

    const int myh = (lane >> 2) & 7;
    #pragma unroll
    for (int j = 0; j < 9; j++) {
        float4 tz = make_float4(t[j].x*z.x, t[j].y*z.y, t[j].z*z.z, t[j].w*z.w);
        float p[8];
        #pragma unroll
        for (int h = 0; h < 8; h++) {
            float4 uu = us[h][lane];
            p[h] = tz.x*uu.x + tz.y*uu.y + tz.z*uu.z + tz.w*uu.w;
        }
        // value-splitting butterfly: 8 items -> 1 per lane quad (all shfls lane-uniform)
        {
            bool up = (lane & 16);
            float q[4];
            #pragma unroll
            for (int i = 0; i < 4; i++) {
                float got = __shfl_xor_sync(0xffffffffu, p[(up ? 0 : 4) + i], 16);
                q[i] = p[(up ? 4 : 0) + i] + got;
            }
            bool up8 = (lane & 8);
            float q2[2];
            #pragma unroll
            for (int i = 0; i < 2; i++) {
                float got = __shfl_xor_sync(0xffffffffu, q[(up8 ? 0 : 2) + i], 8);
                q2[i] = q[(up8 ? 2 : 0) + i] + got;
            }
            bool up4 = (lane & 4);
            float got = __shfl_xor_sync(0xffffffffu, q2[up4 ? 0 : 1], 4);
            float v = q2[up4 ? 1 : 0] + got;
            v += __shfl_xor_sync(0xffffffffu, v, 1);
            v += __shfl_xor_sync(0xffffffffu, v, 2);
            if ((lane & 3) == 0)
                g_S[(size_t)e*72 + j*8 + myh] = v;
        }
    }
}

// ------------------------- logits + segment max -------------------------
__global__ void k_logits(const float* __restrict__ avec, const int* __restrict__ dst)
{
    const int warp = threadIdx.x >> 5, lane = threadIdx.x & 31;
    const int e = blockIdx.x * 8 + warp;
    if (e >= EE) return;
    const float4* ap = (const float4*)(g_abuf + (size_t)e*256) + lane*2;
    const float4* vp = (const float4*)avec + lane*2;
    float4 a0 = ap[0], a1 = ap[1];
    float4 v0 = vp[0], v1 = vp[1];
    #define LR(x) ((x) > 0.f ? (x) : 0.2f*(x))
    float p = LR(a0.x)*v0.x + LR(a0.y)*v0.y + LR(a0.z)*v0.z + LR(a0.w)*v0.w
            + LR(a1.x)*v1.x + LR(a1.y)*v1.y + LR(a1.z)*v1.z + LR(a1.w)*v1.w;
    #undef LR
    p += __shfl_xor_sync(0xffffffffu, p, 1);
    p += __shfl_xor_sync(0xffffffffu, p, 2);
    if ((lane & 3) == 0) {
        int h = lane >> 2;
        g_logits[(size_t)e*8 + h] = p;
        atomicMaxFloat(&g_m[dst[e]*8 + h], p);
    }
}

__global__ void k_expsum(const int* __restrict__ dst)
{
    int tid = blockIdx.x * blockDim.x + threadIdx.x;
    if (tid >= EE*8) return;
    int e = tid >> 3, h = tid & 7;
    int d = dst[e];
    float ex = __expf(g_logits[tid] - g_m[d*8 + h]);
    g_ex[tid] = ex;
    atomicAdd(&g_den[d*8 + h], ex);
}

// ------------------------- pass 2: attn -> R_j -> wigner gram -> scatter -------------------------
__global__ __launch_bounds__(256)
void k_edge_out2(const float* __restrict__ wigner,
                 const int* __restrict__ dst, float* __restrict__ outp)
{
    const int warp = threadIdx.x >> 5, lane = threadIdx.x & 31;
    const int e = blockIdx.x * 8 + warp;
    if (e >= EE) return;
    const int d = dst[e];

    float attn = 0.f;
    if (lane < 8) attn = g_ex[(size_t)e*8 + lane] / (g_den[d*8 + lane] + 1e-9f);

    float R = 0.f;
    {
        const float* Sp = g_S + (size_t)e*72 + lane*8;
        #pragma unroll
        for (int h = 0; h < 8; h++) {
            float ah = __shfl_sync(0xffffffffu, attn, h);
            float sv = 0.f;
            if (lane < 9) sv = Sp[h];
            R += ah * sv;
        }
    }

    float c = 0.f;
    {
        const float* wl = wigner + (size_t)e*81 + lane*9;
        #pragma unroll
        for (int j = 0; j < 9; j++) {
            float Rj = __shfl_sync(0xffffffffu, R, j);
            if (lane < 9) c += wl[j] * Rj;
        }
    }

    float o = 0.f;
    {
        #pragma unroll
        for (int l = 0; l < 9; l++) {
            float cl = __shfl_sync(0xffffffffu, c, l);
            if (lane < 3) o += wigner[(size_t)e*81 + l*9 + (lane + 1)] * cl;
        }
    }
    if (lane < 3) atomicAdd(&outp[d*3 + lane], o);
}

// ------------------------- final select -------------------------
__global__ void k_final(const unsigned char* __restrict__ mask, float* __restrict__ out)
{
    int tid = blockIdx.x * blockDim.x + threadIdx.x;
    if (tid >= NN*3) return;
    int n = tid / 3;
    unsigned int info = g_maskinfo[0];
    bool mk;
    if (info & 2u)      mk = (((const float*)mask)[n] != 0.f);
    else if (info & 1u) mk = (mask[n] != 0);
    else                mk = (((const int*)mask)[n] != 0);
    out[tid] = mk ? g_outd[tid] : g_outv[tid];
}

// ------------------------- host launch -------------------------
extern "C" void kernel_launch(void* const* d_in, const int* in_sizes, int n_in,
                              void* d_out, int out_size)
{
    float *pY, *pWmsgC, *pHidden, *pRad, *pMsg0, *pA, *pOutv, *pOutd;
    cudaGetSymbolAddress((void**)&pY, g_Y);
    cudaGetSymbolAddress((void**)&pWmsgC, g_WmsgC);
    cudaGetSymbolAddress((void**)&pHidden, g_hidden);
    cudaGetSymbolAddress((void**)&pRad, g_rad);
    cudaGetSymbolAddress((void**)&pMsg0, g_msg0);
    cudaGetSymbolAddress((void**)&pA, g_abuf);
    cudaGetSymbolAddress((void**)&pOutv, g_outv);
    cudaGetSymbolAddress((void**)&pOutd, g_outd);

    const float* node_emb  = (const float*)d_in[0];
    const float* edge_dist = (const float*)d_in[1];
    const float* wigner    = (const float*)d_in[2];
    const int *atomic_numbers, *edge_index;
    const void* mask;
    int pbase[2];
    bool dictOrder = (in_sizes[3] == NN);
    if (dictOrder) {
        atomic_numbers = (const int*)d_in[3];
        edge_index     = (const int*)d_in[4];
        mask           = d_in[5];
        pbase[0] = 6; pbase[1] = 14;
    } else {
        pbase[0] = 3; pbase[1] = 11;
        atomic_numbers = (const int*)d_in[19];
        edge_index     = (const int*)d_in[20];
        mask           = d_in[21];
    }
    const int* src = edge_index;
    const int* dst = edge_index + EE;

    k_init0<<<(NN*3 + 255)/256, 256>>>();
    k_detect_mask<<<(NN/4 + 255)/256, 256>>>((const unsigned int*)mask);

    for (int t = 0; t < 2; t++) {
        int b = pbase[t];
        const float* ae     = (const float*)d_in[b + 0];
        const float* Wrad1  = (const float*)d_in[b + 1];
        const float* Wrad2  = (const float*)d_in[b + 2];
        const float* Wmsg   = (const float*)d_in[b + 3];
        const float* Walpha = (const float*)d_in[b + 4];
        const float* avec   = (const float*)d_in[b + 5];
        const float* Wval   = (const float*)d_in[b + 6];
        const float* Wproj  = (const float*)d_in[b + 7];

        k_pack_wmsg<<<128, 256>>>(Wmsg);
        // Y GEMM at global launch #4 so the ncu window samples it again (A/B vs R8 profile)
        k_gemm_tc<0><<<dim3((NLROWS + 127)/128, 2), 256>>>(node_emb, 128, pWmsgC, 256, pY, 256, NLROWS,
                                                           nullptr, nullptr, nullptr);
        k_zemb<<<100, 128>>>(ae, Wrad1);
        k_uvec<<<8, 128>>>(Wval, Wproj);

        k_gemm_tc<1><<<dim3((EE + 127)/128, 1), 256>>>(edge_dist, 128, Wrad1, 128, pHidden, 128, EE,
                                                       src, dst, atomic_numbers);
        k_gemm_tc<0><<<dim3((EE + 127)/128, 1), 256>>>(pHidden, 128, Wrad2, 128, pRad, 128, EE,
                                                       nullptr, nullptr, nullptr);
        k_fuse1<<<(EE + 7)/8, 256>>>(wigner, src, dst);
        k_gemm_tc<0><<<dim3((EE + 127)/128, 2), 256>>>(pMsg0, 128, Walpha, 256, pA, 256, EE,
                                                       nullptr, nullptr, nullptr);
        k_init_mden<<<(NN*8 + 255)/256, 256>>>();
        k_logits<<<(EE + 7)/8, 256>>>(avec, dst);
        k_expsum<<<(EE*8 + 255)/256, 256>>>(dst);
        k_edge_out2<<<(EE + 7)/8, 256>>>(wigner, dst, (t == 0) ? pOutv : pOutd);
    }

    k_final<<<(NN*3 + 255)/256, 256>>>((const unsigned char*)mask, (float*)d_out);
}